// round 1
// baseline (speedup 1.0000x reference)
#include <cuda_runtime.h>
#include <cuda_bf16.h>

#define T_STEPS 1000
#define BETA_1 1e-4f
#define BETA_T 0.02f

// Precomputed (sqrt(alpha_bar), sqrt(1-alpha_bar)) for t_s = 1..T (index 0..T-1)
__device__ float2 g_scales[T_STEPS];

__global__ void init_scales_kernel() {
    // Single thread serial cumprod — ~1000 iterations, negligible vs main kernel.
    if (threadIdx.x == 0 && blockIdx.x == 0) {
        const float slope = (BETA_T - BETA_1) / (float)(T_STEPS - 1);
        float ab = 1.0f;
        for (int i = 0; i < T_STEPS; ++i) {
            float beta = BETA_1 + slope * (float)i;
            ab *= (1.0f - beta);
            g_scales[i] = make_float2(sqrtf(ab), sqrtf(1.0f - ab));
        }
    }
}

// One block per image; 196 threads; each thread handles one float4 (784 = 196*4).
__global__ void __launch_bounds__(196) ddpm_mix_kernel(
    const float4* __restrict__ images,
    const float4* __restrict__ e,
    const int* __restrict__ t,
    float4* __restrict__ out)
{
    const int b = blockIdx.x;
    // reference uses t_s = t + 1, alpha_bar = alpha_bar_all[t_s - 1] = alpha_bar_all[t]
    const int ti = __ldg(&t[b]);
    const float2 sc = g_scales[ti];
    const float sa = sc.x;   // sqrt(alpha_bar)
    const float sb = sc.y;   // sqrt(1 - alpha_bar)

    const long long idx = (long long)b * 196 + threadIdx.x;
    float4 im = __ldg(&images[idx]);
    float4 ee = __ldg(&e[idx]);
    float4 o;
    o.x = fmaf(sa, im.x, sb * ee.x);
    o.y = fmaf(sa, im.y, sb * ee.y);
    o.z = fmaf(sa, im.z, sb * ee.z);
    o.w = fmaf(sa, im.w, sb * ee.w);
    out[idx] = o;
}

extern "C" void kernel_launch(void* const* d_in, const int* in_sizes, int n_in,
                              void* d_out, int out_size) {
    const float4* images = (const float4*)d_in[0];
    const float4* e      = (const float4*)d_in[1];
    const int*    t      = (const int*)d_in[2];
    float4* out          = (float4*)d_out;

    const int B = in_sizes[2];  // t has B elements

    init_scales_kernel<<<1, 32>>>();
    ddpm_mix_kernel<<<B, 196>>>(images, e, t, out);
}

// round 3
// speedup vs baseline: 1.6341x; 1.6341x over previous
#include <cuda_runtime.h>
#include <cuda_bf16.h>

#define T_STEPS 1000
#define BETA_1 1e-4
#define BETA_T 0.02

// ---- compile-time table: (sqrt(alpha_bar[t]), sqrt(1-alpha_bar[t])) ----

struct ScaleTable {
    float2 v[T_STEPS];
};

constexpr double csqrt(double x) {
    // Newton-Raphson; converges in < 40 iters for x in (0, 2)
    double g = x > 1.0 ? x : 1.0;
    for (int i = 0; i < 60; ++i) g = 0.5 * (g + x / g);
    return g;
}

constexpr ScaleTable make_table() {
    ScaleTable tbl{};
    const double slope = (BETA_T - BETA_1) / (double)(T_STEPS - 1);
    double ab = 1.0;
    for (int i = 0; i < T_STEPS; ++i) {
        double beta = BETA_1 + slope * (double)i;
        ab *= (1.0 - beta);
        tbl.v[i].x = (float)csqrt(ab);
        tbl.v[i].y = (float)csqrt(1.0 - ab);
    }
    return tbl;
}

__constant__ ScaleTable g_scales = make_table();

// ---- mix kernel: flat float4 indexing, full warps ----
// total float4 elements = B * 196 (784 floats per image = 196 float4)

__global__ void __launch_bounds__(256) ddpm_mix_kernel(
    const float4* __restrict__ images,
    const float4* __restrict__ e,
    const int* __restrict__ t,
    float4* __restrict__ out,
    int total4)
{
    const int idx = blockIdx.x * 256 + threadIdx.x;
    if (idx >= total4) return;

    const unsigned b = (unsigned)idx / 196u;   // magic-mul division
    const int ti = __ldg(&t[b]);               // alpha_bar index = t (t_s-1 = t)
    const float2 sc = g_scales.v[ti];
    const float sa = sc.x;
    const float sb = sc.y;

    float4 im = __ldg(&images[idx]);
    float4 ee = __ldg(&e[idx]);
    float4 o;
    o.x = fmaf(sa, im.x, sb * ee.x);
    o.y = fmaf(sa, im.y, sb * ee.y);
    o.z = fmaf(sa, im.z, sb * ee.z);
    o.w = fmaf(sa, im.w, sb * ee.w);
    out[idx] = o;
}

extern "C" void kernel_launch(void* const* d_in, const int* in_sizes, int n_in,
                              void* d_out, int out_size) {
    const float4* images = (const float4*)d_in[0];
    const float4* e      = (const float4*)d_in[1];
    const int*    t      = (const int*)d_in[2];
    float4* out          = (float4*)d_out;

    const int B = in_sizes[2];
    const int total4 = B * 196;
    const int grid = (total4 + 255) / 256;

    ddpm_mix_kernel<<<grid, 256>>>(images, e, t, out, total4);
}